// round 1
// baseline (speedup 1.0000x reference)
#include <cuda_runtime.h>

#define Dd 16
#define Hh 64
#define BATCH 32768
#define ROWS 16
#define NTHREADS 256

// dynamic smem layout (floats):
//  sM0[16*64], sM0T[64*16], sM1[64*64], sM2[64*64], sM3[64*16],
//  sc0[64] sc1[64] sc2[64] sc3[16], ss0[64] ss1[64] ss2[64] ss3[16],
//  hA[ROWS*64], hB[ROWS*64], sd0[ROWS*64], sd1[ROWS*64]
#define SMEM_FLOATS (1024 + 1024 + 4096 + 4096 + 1024 + (64*3+16) + (64*3+16) + 4*ROWS*64)
#define SMEM_BYTES (SMEM_FLOATS * 4)

__device__ __forceinline__ float sigm(float x) {
    return __fdividef(1.f, 1.f + __expf(-x));
}

__device__ __forceinline__ float tanh_f(float x) {
    x = fminf(fmaxf(x, -15.f), 15.f);
    float e = __expf(-2.f * x);
    return __fdividef(1.f - e, 1.f + e);
}

__global__ __launch_bounds__(NTHREADS, 1)
void traj_kernel(const float* __restrict__ ts, const float* __restrict__ x0,
    const float* __restrict__ W0, const float* __restrict__ b0, const float* __restrict__ g0, const float* __restrict__ gb0, const float* __restrict__ hb0,
    const float* __restrict__ W1, const float* __restrict__ b1, const float* __restrict__ g1, const float* __restrict__ gb1, const float* __restrict__ hb1,
    const float* __restrict__ W2, const float* __restrict__ b2, const float* __restrict__ g2, const float* __restrict__ gb2, const float* __restrict__ hb2,
    const float* __restrict__ W3, const float* __restrict__ b3, const float* __restrict__ g3, const float* __restrict__ gb3, const float* __restrict__ hb3,
    float* __restrict__ out)
{
    extern __shared__ float sm[];
    float* sM0  = sm;              // [16][64] forward layer0
    float* sM0T = sM0  + 1024;     // [64][16] tangent init (transposed)
    float* sM1  = sM0T + 1024;     // [64][64]
    float* sM2  = sM1  + 4096;     // [64][64]
    float* sM3  = sM2  + 4096;     // [64][16]
    float* sc0  = sM3  + 1024;     // bias terms b*s + t*hb
    float* sc1  = sc0  + 64;
    float* sc2  = sc1  + 64;
    float* sc3  = sc2  + 64;       // [16]
    float* ss0  = sc3  + 16;       // gates sigmoid(t*g+gb)
    float* ss1  = ss0  + 64;
    float* ss2  = ss1  + 64;
    float* ss3  = ss2  + 64;       // [16]
    float* hA   = ss3  + 16;       // [ROWS][64]
    float* hB   = hA   + ROWS * 64;
    float* sd0  = hB   + ROWS * 64;
    float* sd1  = sd0  + ROWS * 64;

    const int tid = threadIdx.x;
    const int row = tid >> 4;      // row within block (0..15)
    const int tx  = tid & 15;      // thread within row; owns tangent row tx
    const int grow = blockIdx.x * ROWS + row;

    float* hArow = hA + row * 64;
    float* hBrow = hB + row * 64;
    float* d0row = sd0 + row * 64;
    float* d1row = sd1 + row * 64;

    const float ts0 = ts[0], ts1 = ts[1], ts2 = ts[2];
    const float tsteps[3] = {ts0, ts1, ts2};

    float x_state = x0[grow * Dd + tx];
    float l_state = 0.f, v_state = 0.f;

    // xs at t index 0 is x0 itself
    out[grow * Dd + tx] = x_state;

    #pragma unroll 1
    for (int step = 0; step < 2; ++step) {
        const float tA = tsteps[step];
        const float hstep = tsteps[step + 1] - tA;
        float ksx = 0.f, ksl = 0.f, ksv = 0.f, kx_prev = 0.f;

        #pragma unroll 1
        for (int stage = 0; stage < 4; ++stage) {
            const float coef = (stage == 0) ? 0.f : ((stage == 3) ? hstep : 0.5f * hstep);
            const float t = tA + coef;   // RK4 stage time offset == input coef here
            const float w = (stage == 1 || stage == 2) ? 2.f : 1.f;

            __syncthreads();   // previous stage's smem uses done

            // ---- build per-t gate vectors and bias terms ----
            if (tid < 64) {
                float a0 = sigm(t * g0[tid] + gb0[tid]);
                float a1 = sigm(t * g1[tid] + gb1[tid]);
                float a2 = sigm(t * g2[tid] + gb2[tid]);
                ss0[tid] = a0;  sc0[tid] = b0[tid] * a0 + t * hb0[tid];
                ss1[tid] = a1;  sc1[tid] = b1[tid] * a1 + t * hb1[tid];
                ss2[tid] = a2;  sc2[tid] = b2[tid] * a2 + t * hb2[tid];
                if (tid < 16) {
                    float a3 = sigm(t * g3[tid] + gb3[tid]);
                    ss3[tid] = a3;  sc3[tid] = b3[tid] * a3 + t * hb3[tid];
                }
            }
            __syncthreads();

            // ---- build M_l = W_l * diag(s_l) in smem ----
            #pragma unroll 1
            for (int i = tid; i < 1024; i += NTHREADS) {
                float v = W0[i] * ss0[i & 63];
                sM0[i] = v;
                sM0T[(i & 63) * 16 + (i >> 6)] = v;
            }
            #pragma unroll 1
            for (int i = tid; i < 4096; i += NTHREADS) sM1[i] = W1[i] * ss1[i & 63];
            #pragma unroll 1
            for (int i = tid; i < 4096; i += NTHREADS) sM2[i] = W2[i] * ss2[i & 63];
            #pragma unroll 1
            for (int i = tid; i < 1024; i += NTHREADS) sM3[i] = W3[i] * ss3[i & 15];
            __syncthreads();

            // ---- stage input ----
            const float xe = x_state + coef * kx_prev;
            hArow[tx] = xe;    // x lives in hA[0..15]
            __syncthreads();

            // ---- forward L0: x(hA[0:16]) -> h1(hB) + d0 ----
            #pragma unroll
            for (int k = 0; k < 4; ++k) {
                const int c = tx + 16 * k;
                float acc = sc0[c];
                #pragma unroll
                for (int j = 0; j < 16; ++j) acc = fmaf(hArow[j], sM0[j * 64 + c], acc);
                float th = tanh_f(acc);
                hBrow[c] = th;
                d0row[c] = 1.f - th * th;
            }
            __syncthreads();

            // ---- forward L1: h1(hB) -> h2(hA) + d1 ----
            #pragma unroll
            for (int k = 0; k < 4; ++k) {
                const int c = tx + 16 * k;
                float acc = sc1[c];
                #pragma unroll 8
                for (int b = 0; b < 64; ++b) acc = fmaf(hBrow[b], sM1[b * 64 + c], acc);
                float th = tanh_f(acc);
                hArow[c] = th;
                d1row[c] = 1.f - th * th;
            }
            __syncthreads();

            // ---- forward L2: h2(hA) -> h3 (regs), d2 (regs) ----
            float h3v[4], d2v[4];
            #pragma unroll
            for (int k = 0; k < 4; ++k) {
                const int c = tx + 16 * k;
                float acc = sc2[c];
                #pragma unroll 8
                for (int b = 0; b < 64; ++b) acc = fmaf(hArow[b], sM2[b * 64 + c], acc);
                float th = tanh_f(acc);
                h3v[k] = th;
                d2v[k] = 1.f - th * th;
            }
            __syncthreads();
            // hA (h2) now dead: park h3 in hB, d2 in hA
            #pragma unroll
            for (int k = 0; k < 4; ++k) {
                const int c = tx + 16 * k;
                hBrow[c] = h3v[k];
                hArow[c] = d2v[k];
            }
            __syncthreads();

            // ---- forward L3 (no tanh): dx[tx] ----
            float dx = sc3[tx];
            #pragma unroll 8
            for (int b = 0; b < 64; ++b) dx = fmaf(hBrow[b], sM3[b * 16 + tx], dx);
            float dvv = dx * dx;

            // ---- tangent: U2 = ((M0T[:,tx] .* d0) @ M1) .* d1   (64 floats in regs) ----
            float U2[64];
            #pragma unroll
            for (int hh = 0; hh < 2; ++hh) {
                const int off = hh * 32;
                float acc[32];
                #pragma unroll
                for (int c = 0; c < 32; ++c) acc[c] = 0.f;
                #pragma unroll 4
                for (int b = 0; b < 64; ++b) {
                    const float u = sM0T[b * 16 + tx] * d0row[b];
                    const float4* m1 = reinterpret_cast<const float4*>(sM1 + b * 64 + off);
                    #pragma unroll
                    for (int q = 0; q < 8; ++q) {
                        float4 m = m1[q];
                        acc[4 * q + 0] = fmaf(u, m.x, acc[4 * q + 0]);
                        acc[4 * q + 1] = fmaf(u, m.y, acc[4 * q + 1]);
                        acc[4 * q + 2] = fmaf(u, m.z, acc[4 * q + 2]);
                        acc[4 * q + 3] = fmaf(u, m.w, acc[4 * q + 3]);
                    }
                }
                #pragma unroll
                for (int c = 0; c < 32; ++c) U2[off + c] = acc[c] * d1row[off + c];
            }

            // ---- tangent: dl_tx = sum_c (U2 @ M2)[c] * d2[c] * M3[c][tx] ----
            float dl = 0.f;
            #pragma unroll
            for (int hh = 0; hh < 2; ++hh) {
                const int off = hh * 32;
                float acc[32];
                #pragma unroll
                for (int c = 0; c < 32; ++c) acc[c] = 0.f;
                #pragma unroll 4
                for (int b = 0; b < 64; ++b) {
                    const float u = U2[b];
                    const float4* m2 = reinterpret_cast<const float4*>(sM2 + b * 64 + off);
                    #pragma unroll
                    for (int q = 0; q < 8; ++q) {
                        float4 m = m2[q];
                        acc[4 * q + 0] = fmaf(u, m.x, acc[4 * q + 0]);
                        acc[4 * q + 1] = fmaf(u, m.y, acc[4 * q + 1]);
                        acc[4 * q + 2] = fmaf(u, m.z, acc[4 * q + 2]);
                        acc[4 * q + 3] = fmaf(u, m.w, acc[4 * q + 3]);
                    }
                }
                #pragma unroll
                for (int c = 0; c < 32; ++c)
                    dl = fmaf(acc[c] * hArow[off + c], sM3[(off + c) * 16 + tx], dl);
            }

            // ---- reduce dl and |dx|^2 over the 16 lanes of this row ----
            #pragma unroll
            for (int m = 8; m >= 1; m >>= 1) {
                dl  += __shfl_xor_sync(0xffffffffu, dl, m);
                dvv += __shfl_xor_sync(0xffffffffu, dvv, m);
            }
            dvv *= 0.5f;

            ksx += w * dx;
            ksl += w * dl;
            ksv += w * dvv;
            kx_prev = dx;
        }

        const float scl = hstep * (1.f / 6.f);
        x_state += scl * ksx;
        l_state += scl * ksl;
        v_state += scl * ksv;
        out[(step + 1) * BATCH * Dd + grow * Dd + tx] = x_state;
    }

    if (tx == 0) {
        const int base = 3 * BATCH * Dd;
        out[base + grow] = l_state;                 // log_det
        out[base + BATCH + grow] = fabsf(v_state);  // loss_L
        out[base + 2 * BATCH + grow] = 0.f;         // zeros
    }
}

extern "C" void kernel_launch(void* const* d_in, const int* in_sizes, int n_in,
                              void* d_out, int out_size) {
    const float* ts  = (const float*)d_in[0];
    const float* x0  = (const float*)d_in[1];
    const float* W0  = (const float*)d_in[2];
    const float* b0  = (const float*)d_in[3];
    const float* g0  = (const float*)d_in[4];
    const float* gb0 = (const float*)d_in[5];
    const float* hb0 = (const float*)d_in[6];
    const float* W1  = (const float*)d_in[7];
    const float* b1  = (const float*)d_in[8];
    const float* g1  = (const float*)d_in[9];
    const float* gb1 = (const float*)d_in[10];
    const float* hb1 = (const float*)d_in[11];
    const float* W2  = (const float*)d_in[12];
    const float* b2  = (const float*)d_in[13];
    const float* g2  = (const float*)d_in[14];
    const float* gb2 = (const float*)d_in[15];
    const float* hb2 = (const float*)d_in[16];
    const float* W3  = (const float*)d_in[17];
    const float* b3  = (const float*)d_in[18];
    const float* g3  = (const float*)d_in[19];
    const float* gb3 = (const float*)d_in[20];
    const float* hb3 = (const float*)d_in[21];
    float* out = (float*)d_out;

    cudaFuncSetAttribute(traj_kernel, cudaFuncAttributeMaxDynamicSharedMemorySize, SMEM_BYTES);

    dim3 grid(BATCH / ROWS);
    dim3 block(NTHREADS);
    traj_kernel<<<grid, block, SMEM_BYTES>>>(
        ts, x0,
        W0, b0, g0, gb0, hb0,
        W1, b1, g1, gb1, hb1,
        W2, b2, g2, gb2, hb2,
        W3, b3, g3, gb3, hb3,
        out);
}

// round 2
// speedup vs baseline: 1.1741x; 1.1741x over previous
#include <cuda_runtime.h>

#define Dd 16
#define BATCH 32768
#define ROWS 8            // batch rows per block; one warp per row
#define NTHREADS 256

typedef unsigned long long ull;

// per-stage constant block layout (floats)
#define O_M0   0
#define O_M0T  1024
#define O_M1   2048
#define O_M2   6144
#define O_M3   10240
#define O_C0   11264
#define O_C1   11328
#define O_C2   11392
#define O_C3   11456
#define ST_FLOATS 11472

// dynamic smem: one stage block + per-row buffers
#define SMEM_FLOATS (ST_FLOATS + 4 * ROWS * 64)
#define SMEM_BYTES (SMEM_FLOATS * 4)

__device__ float g_M[8 * ST_FLOATS];   // 8 RK stages of prebuilt matrices

__device__ __forceinline__ float sigm(float x) {
    return __fdividef(1.f, 1.f + __expf(-x));
}
__device__ __forceinline__ float tanh_f(float x) {
    x = fminf(fmaxf(x, -15.f), 15.f);
    float e = __expf(-2.f * x);
    return __fdividef(1.f - e, 1.f + e);
}

__device__ __forceinline__ ull pk2(float lo, float hi) {
    ull r; asm("mov.b64 %0,{%1,%2};" : "=l"(r) : "f"(lo), "f"(hi)); return r;
}
__device__ __forceinline__ ull pkdup(float v) { return pk2(v, v); }
__device__ __forceinline__ void upk(ull v, float& lo, float& hi) {
    asm("mov.b64 {%0,%1},%2;" : "=f"(lo), "=f"(hi) : "l"(v));
}
__device__ __forceinline__ ull ffma2(ull a, ull b, ull c) {
    ull d; asm("fma.rn.f32x2 %0,%1,%2,%3;" : "=l"(d) : "l"(a), "l"(b), "l"(c)); return d;
}
__device__ __forceinline__ ull fmul2(ull a, ull b) {
    ull d; asm("mul.rn.f32x2 %0,%1,%2;" : "=l"(d) : "l"(a), "l"(b)); return d;
}

// ---------------- pre-kernel: build M_l(t), c_l(t) for the 8 RK stages ----------------
__global__ void build_kernel(const float* __restrict__ ts,
    const float* __restrict__ W0, const float* __restrict__ b0, const float* __restrict__ g0, const float* __restrict__ gb0, const float* __restrict__ hb0,
    const float* __restrict__ W1, const float* __restrict__ b1, const float* __restrict__ g1, const float* __restrict__ gb1, const float* __restrict__ hb1,
    const float* __restrict__ W2, const float* __restrict__ b2, const float* __restrict__ g2, const float* __restrict__ gb2, const float* __restrict__ hb2,
    const float* __restrict__ W3, const float* __restrict__ b3, const float* __restrict__ g3, const float* __restrict__ gb3, const float* __restrict__ hb3)
{
    const int sidx = blockIdx.x;            // 0..7
    const int step = sidx >> 2, stg = sidx & 3;
    const float tA = ts[step];
    const float hstep = ts[step + 1] - tA;
    const float coef = (stg == 0) ? 0.f : ((stg == 3) ? hstep : 0.5f * hstep);
    const float t = tA + coef;
    float* base = g_M + sidx * ST_FLOATS;
    const int tid = threadIdx.x;

    for (int i = tid; i < 1024; i += NTHREADS) {
        int c = i & 63;
        float v = W0[i] * sigm(t * g0[c] + gb0[c]);
        base[O_M0 + i] = v;
        base[O_M0T + c * 16 + (i >> 6)] = v;
    }
    for (int i = tid; i < 4096; i += NTHREADS) {
        int c = i & 63;
        base[O_M1 + i] = W1[i] * sigm(t * g1[c] + gb1[c]);
    }
    for (int i = tid; i < 4096; i += NTHREADS) {
        int c = i & 63;
        base[O_M2 + i] = W2[i] * sigm(t * g2[c] + gb2[c]);
    }
    for (int i = tid; i < 1024; i += NTHREADS) {
        int c = i & 15;
        base[O_M3 + i] = W3[i] * sigm(t * g3[c] + gb3[c]);
    }
    if (tid < 64) {
        float s0 = sigm(t * g0[tid] + gb0[tid]);
        float s1 = sigm(t * g1[tid] + gb1[tid]);
        float s2 = sigm(t * g2[tid] + gb2[tid]);
        base[O_C0 + tid] = b0[tid] * s0 + t * hb0[tid];
        base[O_C1 + tid] = b1[tid] * s1 + t * hb1[tid];
        base[O_C2 + tid] = b2[tid] * s2 + t * hb2[tid];
        if (tid < 16) {
            float s3 = sigm(t * g3[tid] + gb3[tid]);
            base[O_C3 + tid] = b3[tid] * s3 + t * hb3[tid];
        }
    }
}

// ---------------- main kernel ----------------
__global__ __launch_bounds__(NTHREADS, 2)
void traj_kernel(const float* __restrict__ ts, const float* __restrict__ x0,
                 float* __restrict__ out)
{
    extern __shared__ float sm[];
    float* hA  = sm + ST_FLOATS;
    float* hB  = hA + ROWS * 64;
    float* sd0 = hB + ROWS * 64;
    float* sd1 = sd0 + ROWS * 64;

    const int tid  = threadIdx.x;
    const int lane = tid & 31;
    const int wrp  = tid >> 5;          // warp = batch row within block
    const int tx   = lane & 15;         // tangent row owned
    const int hf   = lane >> 4;         // which half of the 64-dim hidden
    const int cbase = hf * 32;
    const int grow = blockIdx.x * ROWS + wrp;
    const int c2 = 2 * lane;            // forward columns (c2, c2+1)

    float* hArow  = hA  + wrp * 64;
    float* hBrow  = hB  + wrp * 64;
    float* sd0row = sd0 + wrp * 64;
    float* sd1row = sd1 + wrp * 64;

    const float ts0 = ts[0], ts1 = ts[1], ts2 = ts[2];
    const float tst[3] = {ts0, ts1, ts2};

    float x_state = (lane < Dd) ? x0[grow * Dd + lane] : 0.f;
    float l_state = 0.f, v_state = 0.f;
    if (lane < Dd) out[grow * Dd + lane] = x_state;

    #pragma unroll 1
    for (int step = 0; step < 2; ++step) {
        const float tA = tst[step];
        const float hstep = tst[step + 1] - tA;
        float ksx = 0.f, ksl = 0.f, ksv = 0.f, kxp = 0.f;

        #pragma unroll 1
        for (int stage = 0; stage < 4; ++stage) {
            __syncthreads();
            if (stage != 2) {   // stage 2 shares t with stage 1 -> same matrices
                const int sidx = step * 4 + stage;
                const float4* __restrict__ src = (const float4*)(g_M + sidx * ST_FLOATS);
                float4* dst = (float4*)sm;
                #pragma unroll 1
                for (int i = tid; i < ST_FLOATS / 4; i += NTHREADS) dst[i] = __ldg(src + i);
            }
            __syncthreads();

            const float coef = (stage == 0) ? 0.f : ((stage == 3) ? hstep : 0.5f * hstep);
            const float wq = (stage == 1 || stage == 2) ? 2.f : 1.f;

            if (lane < Dd) hArow[lane] = x_state + coef * kxp;
            __syncwarp();

            // ---- L0: x (hA[0:16]) -> h1 (hB), d0 ----
            {
                float2 cc = *(const float2*)(sm + O_C0 + c2);
                ull acc = pk2(cc.x, cc.y);
                #pragma unroll
                for (int j = 0; j < 16; ++j) {
                    float hj = hArow[j];
                    float2 m = *(const float2*)(sm + O_M0 + j * 64 + c2);
                    acc = ffma2(pkdup(hj), pk2(m.x, m.y), acc);
                }
                float lo, hi; upk(acc, lo, hi);
                lo = tanh_f(lo); hi = tanh_f(hi);
                *(float2*)(hBrow + c2)  = make_float2(lo, hi);
                *(float2*)(sd0row + c2) = make_float2(1.f - lo * lo, 1.f - hi * hi);
            }
            __syncwarp();

            // ---- L1: h1 (hB) -> h2 (hA), d1 ----
            {
                float2 cc = *(const float2*)(sm + O_C1 + c2);
                ull acc = pk2(cc.x, cc.y);
                #pragma unroll 8
                for (int j = 0; j < 64; ++j) {
                    float hj = hBrow[j];
                    float2 m = *(const float2*)(sm + O_M1 + j * 64 + c2);
                    acc = ffma2(pkdup(hj), pk2(m.x, m.y), acc);
                }
                float lo, hi; upk(acc, lo, hi);
                lo = tanh_f(lo); hi = tanh_f(hi);
                *(float2*)(hArow + c2)  = make_float2(lo, hi);
                *(float2*)(sd1row + c2) = make_float2(1.f - lo * lo, 1.f - hi * hi);
            }
            __syncwarp();

            // ---- L2: h2 (hA) -> h3, d2 (regs) ----
            float h3lo, h3hi, d2lo, d2hi;
            {
                float2 cc = *(const float2*)(sm + O_C2 + c2);
                ull acc = pk2(cc.x, cc.y);
                #pragma unroll 8
                for (int j = 0; j < 64; ++j) {
                    float hj = hArow[j];
                    float2 m = *(const float2*)(sm + O_M2 + j * 64 + c2);
                    acc = ffma2(pkdup(hj), pk2(m.x, m.y), acc);
                }
                float lo, hi; upk(acc, lo, hi);
                h3lo = tanh_f(lo); h3hi = tanh_f(hi);
                d2lo = 1.f - h3lo * h3lo; d2hi = 1.f - h3hi * h3hi;
            }
            __syncwarp();                     // all lanes done reading hArow (h2)
            *(float2*)(hArow + c2) = make_float2(h3lo, h3hi);   // h3
            *(float2*)(hBrow + c2) = make_float2(d2lo, d2hi);   // d2 (h1 dead)
            __syncwarp();

            // ---- L3 (no tanh): dx ----
            float dx = 0.f;
            if (lane < Dd) {
                dx = sm[O_C3 + lane];
                #pragma unroll 8
                for (int b = 0; b < 64; ++b)
                    dx = fmaf(hArow[b], sm[O_M3 + b * 16 + lane], dx);
            }

            // ---- tangent half-U2: U2[c in myhalf] = (sum_a u[a] M1[a,c]) * d1[c] ----
            ull U2a[16];
            #pragma unroll
            for (int q = 0; q < 16; ++q) U2a[q] = 0ull;
            #pragma unroll 4
            for (int a = 0; a < 64; ++a) {
                float ua = sm[O_M0T + a * 16 + tx] * sd0row[a];
                ull ua2 = pkdup(ua);
                const float4* r = (const float4*)(sm + O_M1 + a * 64 + cbase);
                #pragma unroll
                for (int q = 0; q < 8; ++q) {
                    float4 m = r[q];
                    U2a[2 * q]     = ffma2(ua2, pk2(m.x, m.y), U2a[2 * q]);
                    U2a[2 * q + 1] = ffma2(ua2, pk2(m.z, m.w), U2a[2 * q + 1]);
                }
            }
            float U2f[32];
            #pragma unroll
            for (int q = 0; q < 16; ++q) {
                float2 dd = *(const float2*)(sd1row + cbase + 2 * q);
                ull v = fmul2(U2a[q], pk2(dd.x, dd.y));
                upk(v, U2f[2 * q], U2f[2 * q + 1]);
            }

            // ---- z[c in myhalf] = sum_b U2[b] M2[b,c], with shuffle half-exchange ----
            ull zp[16];
            #pragma unroll
            for (int q = 0; q < 16; ++q) zp[q] = 0ull;
            #pragma unroll 1
            for (int pass = 0; pass < 2; ++pass) {
                const int bb = (pass == 0) ? cbase : (32 - cbase);
                if (pass == 1) {
                    #pragma unroll
                    for (int i = 0; i < 32; ++i)
                        U2f[i] = __shfl_xor_sync(0xffffffffu, U2f[i], 16);
                }
                #pragma unroll 4
                for (int i = 0; i < 32; ++i) {
                    ull ub = pkdup(U2f[i]);
                    const float4* r = (const float4*)(sm + O_M2 + (bb + i) * 64 + cbase);
                    #pragma unroll
                    for (int q = 0; q < 8; ++q) {
                        float4 m = r[q];
                        zp[2 * q]     = ffma2(ub, pk2(m.x, m.y), zp[2 * q]);
                        zp[2 * q + 1] = ffma2(ub, pk2(m.z, m.w), zp[2 * q + 1]);
                    }
                }
            }

            // ---- dl partial: sum over my c-half of z[c]*d2[c]*M3[c,tx] ----
            float dl = 0.f;
            #pragma unroll
            for (int q = 0; q < 16; ++q) {
                float zlo, zhi; upk(zp[q], zlo, zhi);
                const int c = cbase + 2 * q;
                float2 d2p = *(const float2*)(hBrow + c);
                dl = fmaf(zlo * d2p.x, sm[O_M3 + c * 16 + tx], dl);
                dl = fmaf(zhi * d2p.y, sm[O_M3 + (c + 1) * 16 + tx], dl);
            }

            // ---- warp reductions ----
            float dv = dx * dx;
            #pragma unroll
            for (int m = 16; m >= 1; m >>= 1) {
                dl += __shfl_xor_sync(0xffffffffu, dl, m);
                dv += __shfl_xor_sync(0xffffffffu, dv, m);
            }
            dv *= 0.5f;

            ksx += wq * dx;
            ksl += wq * dl;
            ksv += wq * dv;
            kxp = dx;
        }

        const float scl = hstep * (1.f / 6.f);
        x_state += scl * ksx;
        l_state += scl * ksl;
        v_state += scl * ksv;
        if (lane < Dd) out[(step + 1) * BATCH * Dd + grow * Dd + lane] = x_state;
    }

    if (lane == 0) {
        const int base = 3 * BATCH * Dd;
        out[base + grow] = l_state;
        out[base + BATCH + grow] = fabsf(v_state);
        out[base + 2 * BATCH + grow] = 0.f;
    }
}

extern "C" void kernel_launch(void* const* d_in, const int* in_sizes, int n_in,
                              void* d_out, int out_size) {
    const float* ts  = (const float*)d_in[0];
    const float* x0  = (const float*)d_in[1];
    const float* W0  = (const float*)d_in[2];
    const float* b0  = (const float*)d_in[3];
    const float* g0  = (const float*)d_in[4];
    const float* gb0 = (const float*)d_in[5];
    const float* hb0 = (const float*)d_in[6];
    const float* W1  = (const float*)d_in[7];
    const float* b1  = (const float*)d_in[8];
    const float* g1  = (const float*)d_in[9];
    const float* gb1 = (const float*)d_in[10];
    const float* hb1 = (const float*)d_in[11];
    const float* W2  = (const float*)d_in[12];
    const float* b2  = (const float*)d_in[13];
    const float* g2  = (const float*)d_in[14];
    const float* gb2 = (const float*)d_in[15];
    const float* hb2 = (const float*)d_in[16];
    const float* W3  = (const float*)d_in[17];
    const float* b3  = (const float*)d_in[18];
    const float* g3  = (const float*)d_in[19];
    const float* gb3 = (const float*)d_in[20];
    const float* hb3 = (const float*)d_in[21];
    float* out = (float*)d_out;

    build_kernel<<<8, NTHREADS>>>(ts,
        W0, b0, g0, gb0, hb0,
        W1, b1, g1, gb1, hb1,
        W2, b2, g2, gb2, hb2,
        W3, b3, g3, gb3, hb3);

    cudaFuncSetAttribute(traj_kernel, cudaFuncAttributeMaxDynamicSharedMemorySize, SMEM_BYTES);
    traj_kernel<<<BATCH / ROWS, NTHREADS, SMEM_BYTES>>>(ts, x0, out);
}

// round 3
// speedup vs baseline: 1.4394x; 1.2260x over previous
#include <cuda_runtime.h>

#define Dd 16
#define BATCH 32768
#define ROWS 8
#define NTHREADS 256

typedef unsigned long long ull;

// stage block layout (floats)
#define O_M0   0
#define O_M0T  1024
#define O_M1   2048
#define O_M2   6144
#define O_M2T  10240
#define O_M3   14336
#define O_M3T  15360
#define O_C0   16384
#define O_C1   16448
#define O_C2   16512
#define O_C3   16576
#define ST_FLOATS 16592

// per-row region: hX 64, hY 64, d0 64, d1 64, d2 64, sUN 1024
#define ROW_FLOATS 1344
#define SMEM_FLOATS (ST_FLOATS + ROWS * ROW_FLOATS)
#define SMEM_BYTES (SMEM_FLOATS * 4)

__device__ float g_M[8 * ST_FLOATS];

__device__ __forceinline__ float sigm(float x) {
    return __fdividef(1.f, 1.f + __expf(-x));
}
__device__ __forceinline__ float tanh_f(float x) {
    x = fminf(fmaxf(x, -15.f), 15.f);
    float e = __expf(-2.f * x);
    return __fdividef(1.f - e, 1.f + e);
}
__device__ __forceinline__ ull pk2(float lo, float hi) {
    ull r; asm("mov.b64 %0,{%1,%2};" : "=l"(r) : "f"(lo), "f"(hi)); return r;
}
__device__ __forceinline__ ull pkdup(float v) { return pk2(v, v); }
__device__ __forceinline__ void upk(ull v, float& lo, float& hi) {
    asm("mov.b64 {%0,%1},%2;" : "=f"(lo), "=f"(hi) : "l"(v));
}
__device__ __forceinline__ ull ffma2(ull a, ull b, ull c) {
    ull d; asm("fma.rn.f32x2 %0,%1,%2,%3;" : "=l"(d) : "l"(a), "l"(b), "l"(c)); return d;
}
__device__ __forceinline__ ull fmul2(ull a, ull b) {
    ull d; asm("mul.rn.f32x2 %0,%1,%2;" : "=l"(d) : "l"(a), "l"(b)); return d;
}
__device__ __forceinline__ ull fadd2(ull a, ull b) {
    ull d; asm("add.rn.f32x2 %0,%1,%2;" : "=l"(d) : "l"(a), "l"(b)); return d;
}

// ---------------- build kernel: M_l(t), transposes, bias vectors for 8 RK stages ----------------
__global__ void build_kernel(const float* __restrict__ ts,
    const float* __restrict__ W0, const float* __restrict__ b0, const float* __restrict__ g0, const float* __restrict__ gb0, const float* __restrict__ hb0,
    const float* __restrict__ W1, const float* __restrict__ b1, const float* __restrict__ g1, const float* __restrict__ gb1, const float* __restrict__ hb1,
    const float* __restrict__ W2, const float* __restrict__ b2, const float* __restrict__ g2, const float* __restrict__ gb2, const float* __restrict__ hb2,
    const float* __restrict__ W3, const float* __restrict__ b3, const float* __restrict__ g3, const float* __restrict__ gb3, const float* __restrict__ hb3)
{
    const int sidx = blockIdx.x;
    const int step = sidx >> 2, stg = sidx & 3;
    const float tA = ts[step];
    const float hstep = ts[step + 1] - tA;
    const float coef = (stg == 0) ? 0.f : ((stg == 3) ? hstep : 0.5f * hstep);
    const float t = tA + coef;
    float* base = g_M + sidx * ST_FLOATS;
    const int tid = threadIdx.x;

    for (int i = tid; i < 1024; i += NTHREADS) {
        int j = i >> 6, c = i & 63;
        float v = W0[i] * sigm(t * g0[c] + gb0[c]);
        base[O_M0 + i] = v;
        base[O_M0T + c * 16 + j] = v;
    }
    for (int i = tid; i < 4096; i += NTHREADS) {
        int c = i & 63;
        base[O_M1 + i] = W1[i] * sigm(t * g1[c] + gb1[c]);
    }
    for (int i = tid; i < 4096; i += NTHREADS) {
        int b = i >> 6, c = i & 63;
        float v = W2[i] * sigm(t * g2[c] + gb2[c]);
        base[O_M2 + i] = v;
        base[O_M2T + c * 64 + b] = v;
    }
    for (int i = tid; i < 1024; i += NTHREADS) {
        int b = i >> 4, e = i & 15;
        float v = W3[i] * sigm(t * g3[e] + gb3[e]);
        base[O_M3 + i] = v;
        base[O_M3T + e * 64 + b] = v;
    }
    if (tid < 64) {
        float s0 = sigm(t * g0[tid] + gb0[tid]);
        float s1 = sigm(t * g1[tid] + gb1[tid]);
        float s2 = sigm(t * g2[tid] + gb2[tid]);
        base[O_C0 + tid] = b0[tid] * s0 + t * hb0[tid];
        base[O_C1 + tid] = b1[tid] * s1 + t * hb1[tid];
        base[O_C2 + tid] = b2[tid] * s2 + t * hb2[tid];
        if (tid < 16) {
            float s3 = sigm(t * g3[tid] + gb3[tid]);
            base[O_C3 + tid] = b3[tid] * s3 + t * hb3[tid];
        }
    }
}

// ---------------- main kernel ----------------
__global__ __launch_bounds__(NTHREADS, 2)
void traj_kernel(const float* __restrict__ ts, const float* __restrict__ x0,
                 float* __restrict__ out)
{
    extern __shared__ float sm[];
    const int tid  = threadIdx.x;
    const int lane = tid & 31;
    const int wrp  = tid >> 5;           // warp == batch row within block
    const int q    = lane & 15;          // column-quad owner (cols 4q..4q+3)
    const int th   = lane >> 4;          // tx half / reduction-dim half
    const int grow = blockIdx.x * ROWS + wrp;

    float* rb   = sm + ST_FLOATS + wrp * ROW_FLOATS;
    float* hX   = rb;          // 64
    float* hY   = rb + 64;     // 64
    float* d0r  = rb + 128;    // 64
    float* d1r  = rb + 192;    // 64
    float* d2r  = rb + 256;    // 64
    float* sUN  = rb + 320;    // 1024: u-matrix, later N-matrix

    const float ts0 = ts[0], ts1 = ts[1], ts2 = ts[2];
    const float tst[3] = {ts0, ts1, ts2};

    // state: dim q (duplicated across th halves)
    float x_state = x0[grow * Dd + q];
    float l_state = 0.f, v_state = 0.f;
    if (th == 0) out[grow * Dd + q] = x_state;

    #pragma unroll 1
    for (int step = 0; step < 2; ++step) {
        const float tA = tst[step];
        const float hstep = tst[step + 1] - tA;
        float ksx = 0.f, ksl = 0.f, ksv = 0.f, kxp = 0.f;

        #pragma unroll 1
        for (int stage = 0; stage < 4; ++stage) {
            __syncthreads();
            if (stage != 2) {   // stage 2 shares t (and thus matrices) with stage 1
                const int sidx = step * 4 + stage;
                const float4* __restrict__ src = (const float4*)(g_M + sidx * ST_FLOATS);
                float4* dst = (float4*)sm;
                #pragma unroll 1
                for (int i = tid; i < ST_FLOATS / 4; i += NTHREADS) dst[i] = __ldg(src + i);
            }
            __syncthreads();

            const float coef = (stage == 0) ? 0.f : ((stage == 3) ? hstep : 0.5f * hstep);
            const float wq = (stage == 1 || stage == 2) ? 2.f : 1.f;

            if (th == 0) hX[q] = x_state + coef * kxp;
            __syncwarp();

            // ======== forward L0: x(hX[0:16]) -> h1(hY), d0 ========
            {
                ull a0 = 0ull, a1 = 0ull;
                if (th == 0) {
                    a0 = pk2(sm[O_C0 + 4 * q], sm[O_C0 + 4 * q + 1]);
                    a1 = pk2(sm[O_C0 + 4 * q + 2], sm[O_C0 + 4 * q + 3]);
                }
                #pragma unroll
                for (int jj = 0; jj < 8; ++jj) {
                    const int j = 8 * th + jj;
                    const float hj = hX[j];
                    const float4 m = *(const float4*)(sm + O_M0 + j * 64 + 4 * q);
                    const ull hd = pkdup(hj);
                    a0 = ffma2(hd, pk2(m.x, m.y), a0);
                    a1 = ffma2(hd, pk2(m.z, m.w), a1);
                }
                a0 = fadd2(a0, __shfl_xor_sync(0xffffffffu, a0, 16));
                a1 = fadd2(a1, __shfl_xor_sync(0xffffffffu, a1, 16));
                if (th == 0) {
                    float v0, v1, v2, v3; upk(a0, v0, v1); upk(a1, v2, v3);
                    v0 = tanh_f(v0); v1 = tanh_f(v1); v2 = tanh_f(v2); v3 = tanh_f(v3);
                    *(float4*)(hY + 4 * q)  = make_float4(v0, v1, v2, v3);
                    *(float4*)(d0r + 4 * q) = make_float4(1.f - v0 * v0, 1.f - v1 * v1,
                                                          1.f - v2 * v2, 1.f - v3 * v3);
                }
                __syncwarp();
            }

            // ======== forward L1: h1(hY) -> h2(hX), d1 ========
            {
                ull a0 = 0ull, a1 = 0ull;
                if (th == 0) {
                    a0 = pk2(sm[O_C1 + 4 * q], sm[O_C1 + 4 * q + 1]);
                    a1 = pk2(sm[O_C1 + 4 * q + 2], sm[O_C1 + 4 * q + 3]);
                }
                #pragma unroll 8
                for (int jj = 0; jj < 32; ++jj) {
                    const int j = 32 * th + jj;
                    const float hj = hY[j];
                    const float4 m = *(const float4*)(sm + O_M1 + j * 64 + 4 * q);
                    const ull hd = pkdup(hj);
                    a0 = ffma2(hd, pk2(m.x, m.y), a0);
                    a1 = ffma2(hd, pk2(m.z, m.w), a1);
                }
                a0 = fadd2(a0, __shfl_xor_sync(0xffffffffu, a0, 16));
                a1 = fadd2(a1, __shfl_xor_sync(0xffffffffu, a1, 16));
                if (th == 0) {
                    float v0, v1, v2, v3; upk(a0, v0, v1); upk(a1, v2, v3);
                    v0 = tanh_f(v0); v1 = tanh_f(v1); v2 = tanh_f(v2); v3 = tanh_f(v3);
                    *(float4*)(hX + 4 * q)  = make_float4(v0, v1, v2, v3);
                    *(float4*)(d1r + 4 * q) = make_float4(1.f - v0 * v0, 1.f - v1 * v1,
                                                          1.f - v2 * v2, 1.f - v3 * v3);
                }
                __syncwarp();
            }

            // ======== forward L2: h2(hX) -> h3(hY), d2 ========
            {
                ull a0 = 0ull, a1 = 0ull;
                if (th == 0) {
                    a0 = pk2(sm[O_C2 + 4 * q], sm[O_C2 + 4 * q + 1]);
                    a1 = pk2(sm[O_C2 + 4 * q + 2], sm[O_C2 + 4 * q + 3]);
                }
                #pragma unroll 8
                for (int jj = 0; jj < 32; ++jj) {
                    const int j = 32 * th + jj;
                    const float hj = hX[j];
                    const float4 m = *(const float4*)(sm + O_M2 + j * 64 + 4 * q);
                    const ull hd = pkdup(hj);
                    a0 = ffma2(hd, pk2(m.x, m.y), a0);
                    a1 = ffma2(hd, pk2(m.z, m.w), a1);
                }
                a0 = fadd2(a0, __shfl_xor_sync(0xffffffffu, a0, 16));
                a1 = fadd2(a1, __shfl_xor_sync(0xffffffffu, a1, 16));
                if (th == 0) {
                    float v0, v1, v2, v3; upk(a0, v0, v1); upk(a1, v2, v3);
                    v0 = tanh_f(v0); v1 = tanh_f(v1); v2 = tanh_f(v2); v3 = tanh_f(v3);
                    *(float4*)(hY + 4 * q)  = make_float4(v0, v1, v2, v3);
                    *(float4*)(d2r + 4 * q) = make_float4(1.f - v0 * v0, 1.f - v1 * v1,
                                                          1.f - v2 * v2, 1.f - v3 * v3);
                }
                __syncwarp();
            }

            // ======== forward L3: h3(hY) -> dx (cols 4q for q<4), no tanh ========
            {
                ull a0 = 0ull, a1 = 0ull;
                if (th == 0 && q < 4) {
                    a0 = pk2(sm[O_C3 + 4 * q], sm[O_C3 + 4 * q + 1]);
                    a1 = pk2(sm[O_C3 + 4 * q + 2], sm[O_C3 + 4 * q + 3]);
                }
                #pragma unroll 8
                for (int jj = 0; jj < 32; ++jj) {
                    const int b = 32 * th + jj;
                    const float hb = hY[b];
                    if (q < 4) {
                        const float4 m = *(const float4*)(sm + O_M3 + b * 16 + 4 * q);
                        const ull hd = pkdup(hb);
                        a0 = ffma2(hd, pk2(m.x, m.y), a0);
                        a1 = ffma2(hd, pk2(m.z, m.w), a1);
                    }
                }
                a0 = fadd2(a0, __shfl_xor_sync(0xffffffffu, a0, 16));
                a1 = fadd2(a1, __shfl_xor_sync(0xffffffffu, a1, 16));
                if (th == 0 && q < 4) {
                    float v0, v1, v2, v3; upk(a0, v0, v1); upk(a1, v2, v3);
                    *(float4*)(hX + 4 * q) = make_float4(v0, v1, v2, v3);  // dx into hX[0:16]
                }
                __syncwarp();
            }
            const float dx = hX[q];      // per-dim dx (dup across th)

            // ======== build u-matrix: sUN[a][tx] = M0T[a][tx] * d0[a] ========
            #pragma unroll
            for (int aa = 0; aa < 2; ++aa) {
                const int a = lane + 32 * aa;
                const float da = d0r[a];
                const float4* src = (const float4*)(sm + O_M0T + a * 16);
                float4* dst = (float4*)(sUN + a * 16);
                #pragma unroll
                for (int k = 0; k < 4; ++k) {
                    float4 v = src[k];
                    dst[k] = make_float4(v.x * da, v.y * da, v.z * da, v.w * da);
                }
            }
            __syncwarp();

            // ======== tangent pass 1: U2[tx][c] = sum_a u[a][tx] * M1[a][c] ========
            ull A[8][2];
            #pragma unroll
            for (int i = 0; i < 8; ++i) { A[i][0] = 0ull; A[i][1] = 0ull; }
            #pragma unroll 4
            for (int a = 0; a < 64; ++a) {
                const float4 m = *(const float4*)(sm + O_M1 + a * 64 + 4 * q);
                const ull m01 = pk2(m.x, m.y), m23 = pk2(m.z, m.w);
                const float4 u0 = *(const float4*)(sUN + a * 16 + 8 * th);
                const float4 u1 = *(const float4*)(sUN + a * 16 + 8 * th + 4);
                ull d;
                d = pkdup(u0.x); A[0][0] = ffma2(d, m01, A[0][0]); A[0][1] = ffma2(d, m23, A[0][1]);
                d = pkdup(u0.y); A[1][0] = ffma2(d, m01, A[1][0]); A[1][1] = ffma2(d, m23, A[1][1]);
                d = pkdup(u0.z); A[2][0] = ffma2(d, m01, A[2][0]); A[2][1] = ffma2(d, m23, A[2][1]);
                d = pkdup(u0.w); A[3][0] = ffma2(d, m01, A[3][0]); A[3][1] = ffma2(d, m23, A[3][1]);
                d = pkdup(u1.x); A[4][0] = ffma2(d, m01, A[4][0]); A[4][1] = ffma2(d, m23, A[4][1]);
                d = pkdup(u1.y); A[5][0] = ffma2(d, m01, A[5][0]); A[5][1] = ffma2(d, m23, A[5][1]);
                d = pkdup(u1.z); A[6][0] = ffma2(d, m01, A[6][0]); A[6][1] = ffma2(d, m23, A[6][1]);
                d = pkdup(u1.w); A[7][0] = ffma2(d, m01, A[7][0]); A[7][1] = ffma2(d, m23, A[7][1]);
            }
            // scale by d1[c]
            {
                const float4 s = *(const float4*)(d1r + 4 * q);
                const ull s01 = pk2(s.x, s.y), s23 = pk2(s.z, s.w);
                #pragma unroll
                for (int i = 0; i < 8; ++i) {
                    A[i][0] = fmul2(A[i][0], s01);
                    A[i][1] = fmul2(A[i][1], s23);
                }
            }

            // ======== build N-matrix (overwrite sUN): N[c][tx] = d2[c] * M3[c][tx] ========
            __syncwarp();
            #pragma unroll
            for (int cc = 0; cc < 2; ++cc) {
                const int c = lane + 32 * cc;
                const float dc = d2r[c];
                const float4* src = (const float4*)(sm + O_M3 + c * 16);
                float4* dst = (float4*)(sUN + c * 16);
                #pragma unroll
                for (int k = 0; k < 4; ++k) {
                    float4 v = src[k];
                    dst[k] = make_float4(v.x * dc, v.y * dc, v.z * dc, v.w * dc);
                }
            }
            __syncwarp();

            // ======== tangent pass 2: W[b][tx] = sum_c M2T[c][b] * N[c][tx] ========
            ull B[8][2];
            #pragma unroll
            for (int i = 0; i < 8; ++i) { B[i][0] = 0ull; B[i][1] = 0ull; }
            #pragma unroll 4
            for (int c = 0; c < 64; ++c) {
                const float4 m = *(const float4*)(sm + O_M2T + c * 64 + 4 * q);
                const ull m01 = pk2(m.x, m.y), m23 = pk2(m.z, m.w);
                const float4 n0 = *(const float4*)(sUN + c * 16 + 8 * th);
                const float4 n1 = *(const float4*)(sUN + c * 16 + 8 * th + 4);
                ull d;
                d = pkdup(n0.x); B[0][0] = ffma2(d, m01, B[0][0]); B[0][1] = ffma2(d, m23, B[0][1]);
                d = pkdup(n0.y); B[1][0] = ffma2(d, m01, B[1][0]); B[1][1] = ffma2(d, m23, B[1][1]);
                d = pkdup(n0.z); B[2][0] = ffma2(d, m01, B[2][0]); B[2][1] = ffma2(d, m23, B[2][1]);
                d = pkdup(n0.w); B[3][0] = ffma2(d, m01, B[3][0]); B[3][1] = ffma2(d, m23, B[3][1]);
                d = pkdup(n1.x); B[4][0] = ffma2(d, m01, B[4][0]); B[4][1] = ffma2(d, m23, B[4][1]);
                d = pkdup(n1.y); B[5][0] = ffma2(d, m01, B[5][0]); B[5][1] = ffma2(d, m23, B[5][1]);
                d = pkdup(n1.z); B[6][0] = ffma2(d, m01, B[6][0]); B[6][1] = ffma2(d, m23, B[6][1]);
                d = pkdup(n1.w); B[7][0] = ffma2(d, m01, B[7][0]); B[7][1] = ffma2(d, m23, B[7][1]);
            }

            // ======== dl = sum_{tx,b} U2[tx][b] * W[b][tx]  (elementwise in regs) ========
            ull dl2 = 0ull;
            #pragma unroll
            for (int i = 0; i < 8; ++i) {
                dl2 = ffma2(A[i][0], B[i][0], dl2);
                dl2 = ffma2(A[i][1], B[i][1], dl2);
            }
            float dlo, dhi; upk(dl2, dlo, dhi);
            float dl = dlo + dhi;
            float dv = (th == 0) ? dx * dx : 0.f;
            #pragma unroll
            for (int m = 16; m >= 1; m >>= 1) {
                dl += __shfl_xor_sync(0xffffffffu, dl, m);
                dv += __shfl_xor_sync(0xffffffffu, dv, m);
            }
            dv *= 0.5f;

            ksx += wq * dx;
            ksl += wq * dl;
            ksv += wq * dv;
            kxp = dx;
        }

        const float scl = hstep * (1.f / 6.f);
        x_state += scl * ksx;
        l_state += scl * ksl;
        v_state += scl * ksv;
        if (th == 0) out[(step + 1) * BATCH * Dd + grow * Dd + q] = x_state;
    }

    if (lane == 0) {
        const int base = 3 * BATCH * Dd;
        out[base + grow] = l_state;
        out[base + BATCH + grow] = fabsf(v_state);
        out[base + 2 * BATCH + grow] = 0.f;
    }
}

extern "C" void kernel_launch(void* const* d_in, const int* in_sizes, int n_in,
                              void* d_out, int out_size) {
    const float* ts  = (const float*)d_in[0];
    const float* x0  = (const float*)d_in[1];
    const float* W0  = (const float*)d_in[2];
    const float* b0  = (const float*)d_in[3];
    const float* g0  = (const float*)d_in[4];
    const float* gb0 = (const float*)d_in[5];
    const float* hb0 = (const float*)d_in[6];
    const float* W1  = (const float*)d_in[7];
    const float* b1  = (const float*)d_in[8];
    const float* g1  = (const float*)d_in[9];
    const float* gb1 = (const float*)d_in[10];
    const float* hb1 = (const float*)d_in[11];
    const float* W2  = (const float*)d_in[12];
    const float* b2  = (const float*)d_in[13];
    const float* g2  = (const float*)d_in[14];
    const float* gb2 = (const float*)d_in[15];
    const float* hb2 = (const float*)d_in[16];
    const float* W3  = (const float*)d_in[17];
    const float* b3  = (const float*)d_in[18];
    const float* g3  = (const float*)d_in[19];
    const float* gb3 = (const float*)d_in[20];
    const float* hb3 = (const float*)d_in[21];
    float* out = (float*)d_out;

    build_kernel<<<8, NTHREADS>>>(ts,
        W0, b0, g0, gb0, hb0,
        W1, b1, g1, gb1, hb1,
        W2, b2, g2, gb2, hb2,
        W3, b3, g3, gb3, hb3);

    cudaFuncSetAttribute(traj_kernel, cudaFuncAttributeMaxDynamicSharedMemorySize, SMEM_BYTES);
    traj_kernel<<<BATCH / ROWS, NTHREADS, SMEM_BYTES>>>(ts, x0, out);
}

// round 4
// speedup vs baseline: 1.8201x; 1.2645x over previous
#include <cuda_runtime.h>

#define Dd 16
#define BATCH 32768
#define ROWS 16           // batch rows per block (2 per warp)
#define NTHREADS 256

typedef unsigned long long ull;

// stage-constant block layout (floats)
#define O_M0   0          // [j][c] 16x64
#define O_M0T  1024       // [a][tx] 64x16
#define O_M1   2048       // [j][c] 64x64
#define O_M2   6144       // [j][c] 64x64
#define O_M2T  10240      // [c][b] 64x64
#define O_M3   14336      // [j][e] 64x16
#define O_C0   15360
#define O_C1   15424
#define O_C2   15488
#define O_C3   15552      // 16
#define ST_FLOATS 15568

#define RP_FLOATS 640     // per warp (2 rows): hX,hY,d0,d1,d2 each 128 (interleaved [i*2+r])
#define SMEM_FLOATS (ST_FLOATS + 8 * RP_FLOATS)
#define SMEM_BYTES (SMEM_FLOATS * 4)

__device__ float g_M[8 * ST_FLOATS];

__device__ __forceinline__ float sigm(float x) {
    return __fdividef(1.f, 1.f + __expf(-x));
}
__device__ __forceinline__ float tanh_f(float x) {
    x = fminf(fmaxf(x, -15.f), 15.f);
    float e = __expf(-2.f * x);
    return __fdividef(1.f - e, 1.f + e);
}
__device__ __forceinline__ ull pk2(float lo, float hi) {
    ull r; asm("mov.b64 %0,{%1,%2};" : "=l"(r) : "f"(lo), "f"(hi)); return r;
}
__device__ __forceinline__ ull pkdup(float v) { return pk2(v, v); }
__device__ __forceinline__ void upk(ull v, float& lo, float& hi) {
    asm("mov.b64 {%0,%1},%2;" : "=f"(lo), "=f"(hi) : "l"(v));
}
__device__ __forceinline__ ull ffma2(ull a, ull b, ull c) {
    ull d; asm("fma.rn.f32x2 %0,%1,%2,%3;" : "=l"(d) : "l"(a), "l"(b), "l"(c)); return d;
}
__device__ __forceinline__ ull fmul2(ull a, ull b) {
    ull d; asm("mul.rn.f32x2 %0,%1,%2;" : "=l"(d) : "l"(a), "l"(b)); return d;
}
__device__ __forceinline__ ull fadd2(ull a, ull b) {
    ull d; asm("add.rn.f32x2 %0,%1,%2;" : "=l"(d) : "l"(a), "l"(b)); return d;
}

// ---------------- build kernel ----------------
__global__ void build_kernel(const float* __restrict__ ts,
    const float* __restrict__ W0, const float* __restrict__ b0, const float* __restrict__ g0, const float* __restrict__ gb0, const float* __restrict__ hb0,
    const float* __restrict__ W1, const float* __restrict__ b1, const float* __restrict__ g1, const float* __restrict__ gb1, const float* __restrict__ hb1,
    const float* __restrict__ W2, const float* __restrict__ b2, const float* __restrict__ g2, const float* __restrict__ gb2, const float* __restrict__ hb2,
    const float* __restrict__ W3, const float* __restrict__ b3, const float* __restrict__ g3, const float* __restrict__ gb3, const float* __restrict__ hb3)
{
    const int sidx = blockIdx.x;
    const int step = sidx >> 2, stg = sidx & 3;
    const float tA = ts[step];
    const float hstep = ts[step + 1] - tA;
    const float coef = (stg == 0) ? 0.f : ((stg == 3) ? hstep : 0.5f * hstep);
    const float t = tA + coef;
    float* base = g_M + sidx * ST_FLOATS;
    const int tid = threadIdx.x;

    for (int i = tid; i < 1024; i += NTHREADS) {
        int j = i >> 6, c = i & 63;
        float v = W0[i] * sigm(t * g0[c] + gb0[c]);
        base[O_M0 + i] = v;
        base[O_M0T + c * 16 + j] = v;
    }
    for (int i = tid; i < 4096; i += NTHREADS) {
        int c = i & 63;
        base[O_M1 + i] = W1[i] * sigm(t * g1[c] + gb1[c]);
    }
    for (int i = tid; i < 4096; i += NTHREADS) {
        int b = i >> 6, c = i & 63;
        float v = W2[i] * sigm(t * g2[c] + gb2[c]);
        base[O_M2 + i] = v;
        base[O_M2T + c * 64 + b] = v;
    }
    for (int i = tid; i < 1024; i += NTHREADS) {
        int e = i & 15;
        base[O_M3 + i] = W3[i] * sigm(t * g3[e] + gb3[e]);
    }
    if (tid < 64) {
        float s0 = sigm(t * g0[tid] + gb0[tid]);
        float s1 = sigm(t * g1[tid] + gb1[tid]);
        float s2 = sigm(t * g2[tid] + gb2[tid]);
        base[O_C0 + tid] = b0[tid] * s0 + t * hb0[tid];
        base[O_C1 + tid] = b1[tid] * s1 + t * hb1[tid];
        base[O_C2 + tid] = b2[tid] * s2 + t * hb2[tid];
        if (tid < 16) {
            float s3 = sigm(t * g3[tid] + gb3[tid]);
            base[O_C3 + tid] = b3[tid] * s3 + t * hb3[tid];
        }
    }
}

// forward layer (JN inputs -> 64 outputs + tanh + deriv); 2 rows per warp.
__device__ __forceinline__ void fwd64(const float* __restrict__ sm,
                                      const float* __restrict__ src, float* __restrict__ dst,
                                      float* __restrict__ db, int Moff, int Coff, int JN,
                                      int fjq, int fcg)
{
    ull acc[8];
    #pragma unroll
    for (int i = 0; i < 8; ++i) acc[i] = 0ull;
    const int niter = JN >> 2;
    #pragma unroll 4
    for (int i = 0; i < niter; ++i) {
        const int j = 4 * i + fjq;
        const float4 m01 = *(const float4*)(sm + Moff + j * 64 + 4 * fcg);
        const float4 m23 = *(const float4*)(sm + Moff + j * 64 + 32 + 4 * fcg);
        const float2 hh = *(const float2*)(src + 2 * j);
        const ull h0 = pkdup(hh.x), h1 = pkdup(hh.y);
        const ull cA = pk2(m01.x, m01.y), cB = pk2(m01.z, m01.w);
        const ull cC = pk2(m23.x, m23.y), cD = pk2(m23.z, m23.w);
        acc[0] = ffma2(h0, cA, acc[0]); acc[1] = ffma2(h0, cB, acc[1]);
        acc[2] = ffma2(h0, cC, acc[2]); acc[3] = ffma2(h0, cD, acc[3]);
        acc[4] = ffma2(h1, cA, acc[4]); acc[5] = ffma2(h1, cB, acc[5]);
        acc[6] = ffma2(h1, cC, acc[6]); acc[7] = ffma2(h1, cD, acc[7]);
    }
    #pragma unroll
    for (int m = 8; m <= 16; m <<= 1) {
        #pragma unroll
        for (int i = 0; i < 8; ++i)
            acc[i] = fadd2(acc[i], __shfl_xor_sync(0xffffffffu, acc[i], m));
    }
    // each lane finishes one column pair (cp = fjq)
    const int cp = fjq;
    const int col0 = (cp < 2) ? (4 * fcg + 2 * cp) : (32 + 4 * fcg + 2 * (cp - 2));
    ull p0 = (cp == 0) ? acc[0] : ((cp == 1) ? acc[1] : ((cp == 2) ? acc[2] : acc[3]));
    ull p1 = (cp == 0) ? acc[4] : ((cp == 1) ? acc[5] : ((cp == 2) ? acc[6] : acc[7]));
    const float2 cb = *(const float2*)(sm + Coff + col0);
    float a0lo, a0hi, a1lo, a1hi;
    upk(p0, a0lo, a0hi); upk(p1, a1lo, a1hi);
    float v00 = tanh_f(a0lo + cb.x), v01 = tanh_f(a0hi + cb.y);
    float v10 = tanh_f(a1lo + cb.x), v11 = tanh_f(a1hi + cb.y);
    *(float2*)(dst + 2 * col0)     = make_float2(v00, v10);
    *(float2*)(dst + 2 * col0 + 2) = make_float2(v01, v11);
    *(float2*)(db  + 2 * col0)     = make_float2(1.f - v00 * v00, 1.f - v10 * v10);
    *(float2*)(db  + 2 * col0 + 2) = make_float2(1.f - v01 * v01, 1.f - v11 * v11);
}

// L3: 64 -> 16, no tanh; dx written to dxbuf[e*2+r]
__device__ __forceinline__ void fwdL3(const float* __restrict__ sm,
                                      const float* __restrict__ src, float* __restrict__ dxbuf,
                                      int fjq, int fcg)
{
    ull a0 = 0ull, a1 = 0ull;
    #pragma unroll 4
    for (int i = 0; i < 16; ++i) {
        const int j = 4 * i + fjq;
        const float2 m = *(const float2*)(sm + O_M3 + j * 16 + 2 * fcg);
        const float2 hh = *(const float2*)(src + 2 * j);
        const ull mm = pk2(m.x, m.y);
        a0 = ffma2(pkdup(hh.x), mm, a0);
        a1 = ffma2(pkdup(hh.y), mm, a1);
    }
    #pragma unroll
    for (int m = 8; m <= 16; m <<= 1) {
        a0 = fadd2(a0, __shfl_xor_sync(0xffffffffu, a0, m));
        a1 = fadd2(a1, __shfl_xor_sync(0xffffffffu, a1, m));
    }
    if (fjq == 0) {
        const float2 cb = *(const float2*)(sm + O_C3 + 2 * fcg);
        float x0l, x0h, x1l, x1h;
        upk(a0, x0l, x0h); upk(a1, x1l, x1h);
        *(float4*)(dxbuf + 4 * fcg) =
            make_float4(x0l + cb.x, x1l + cb.x, x0h + cb.y, x1h + cb.y);
    }
}

// ---------------- main kernel ----------------
__global__ __launch_bounds__(NTHREADS, 2)
void traj_kernel(const float* __restrict__ ts, const float* __restrict__ x0,
                 float* __restrict__ out)
{
    extern __shared__ float sm[];
    const int tid  = threadIdx.x;
    const int lane = tid & 31;
    const int wrp  = tid >> 5;
    const int fjq  = lane >> 3, fcg = lane & 7;          // forward decomposition
    const int tr   = lane >> 4, tth = (lane >> 3) & 1, tcg = lane & 7;  // tangent
    const int sr   = lane >> 4, se  = lane & 15;         // state ownership

    float* rb  = sm + ST_FLOATS + wrp * RP_FLOATS;
    float* hX  = rb;         // [i*2+r]
    float* hY  = rb + 128;
    float* d0b = rb + 256;
    float* d1b = rb + 384;
    float* d2b = rb + 512;

    const int grow0 = blockIdx.x * ROWS + wrp * 2;

    const float ts0 = ts[0], ts1 = ts[1], ts2 = ts[2];
    const float tst[3] = {ts0, ts1, ts2};

    float x_state = x0[(grow0 + sr) * Dd + se];
    float l_state = 0.f, v_state = 0.f;
    out[(grow0 + sr) * Dd + se] = x_state;

    #pragma unroll 1
    for (int step = 0; step < 2; ++step) {
        const float tA = tst[step];
        const float hstep = tst[step + 1] - tA;
        float ksx = 0.f, ksl = 0.f, ksv = 0.f, kxp = 0.f;

        #pragma unroll 1
        for (int stage = 0; stage < 4; ++stage) {
            if (stage != 2) {   // stage 2 shares t with stage 1 -> same matrices
                __syncthreads();
                const int sidx = step * 4 + stage;
                const float4* __restrict__ src = (const float4*)(g_M + sidx * ST_FLOATS);
                float4* dst = (float4*)sm;
                #pragma unroll 1
                for (int i = tid; i < ST_FLOATS / 4; i += NTHREADS) dst[i] = __ldg(src + i);
                __syncthreads();
            }

            const float coef = (stage == 0) ? 0.f : ((stage == 3) ? hstep : 0.5f * hstep);
            const float wq = (stage == 1 || stage == 2) ? 2.f : 1.f;

            hX[2 * se + sr] = x_state + coef * kxp;
            __syncwarp();

            fwd64(sm, hX, hY, d0b, O_M0, O_C0, 16, fjq, fcg);
            __syncwarp();
            fwd64(sm, hY, hX, d1b, O_M1, O_C1, 64, fjq, fcg);
            __syncwarp();
            fwd64(sm, hX, hY, d2b, O_M2, O_C2, 64, fjq, fcg);
            __syncwarp();
            fwdL3(sm, hY, hX, fjq, fcg);        // dx -> hX[e*2+r]
            __syncwarp();

            const float dx = hX[2 * se + sr];

            // ===== tangent pass 1: A[tx][b] = sum_a (M0T[a][tx]*d0[a]) * M1[a][b] =====
            ull A[32];
            #pragma unroll
            for (int i = 0; i < 32; ++i) A[i] = 0ull;
            #pragma unroll 2
            for (int a = 0; a < 64; ++a) {
                const float4 mt0 = *(const float4*)(sm + O_M0T + a * 16 + 8 * tth);
                const float4 mt1 = *(const float4*)(sm + O_M0T + a * 16 + 8 * tth + 4);
                const float dd = d0b[2 * a + tr];
                const float4 m01 = *(const float4*)(sm + O_M1 + a * 64 + 4 * tcg);
                const float4 m23 = *(const float4*)(sm + O_M1 + a * 64 + 32 + 4 * tcg);
                const ull cA = pk2(m01.x, m01.y), cB = pk2(m01.z, m01.w);
                const ull cC = pk2(m23.x, m23.y), cD = pk2(m23.z, m23.w);
                ull ud;
                ud = pkdup(mt0.x * dd);
                A[0]  = ffma2(ud, cA, A[0]);  A[1]  = ffma2(ud, cB, A[1]);
                A[2]  = ffma2(ud, cC, A[2]);  A[3]  = ffma2(ud, cD, A[3]);
                ud = pkdup(mt0.y * dd);
                A[4]  = ffma2(ud, cA, A[4]);  A[5]  = ffma2(ud, cB, A[5]);
                A[6]  = ffma2(ud, cC, A[6]);  A[7]  = ffma2(ud, cD, A[7]);
                ud = pkdup(mt0.z * dd);
                A[8]  = ffma2(ud, cA, A[8]);  A[9]  = ffma2(ud, cB, A[9]);
                A[10] = ffma2(ud, cC, A[10]); A[11] = ffma2(ud, cD, A[11]);
                ud = pkdup(mt0.w * dd);
                A[12] = ffma2(ud, cA, A[12]); A[13] = ffma2(ud, cB, A[13]);
                A[14] = ffma2(ud, cC, A[14]); A[15] = ffma2(ud, cD, A[15]);
                ud = pkdup(mt1.x * dd);
                A[16] = ffma2(ud, cA, A[16]); A[17] = ffma2(ud, cB, A[17]);
                A[18] = ffma2(ud, cC, A[18]); A[19] = ffma2(ud, cD, A[19]);
                ud = pkdup(mt1.y * dd);
                A[20] = ffma2(ud, cA, A[20]); A[21] = ffma2(ud, cB, A[21]);
                A[22] = ffma2(ud, cC, A[22]); A[23] = ffma2(ud, cD, A[23]);
                ud = pkdup(mt1.z * dd);
                A[24] = ffma2(ud, cA, A[24]); A[25] = ffma2(ud, cB, A[25]);
                A[26] = ffma2(ud, cC, A[26]); A[27] = ffma2(ud, cD, A[27]);
                ud = pkdup(mt1.w * dd);
                A[28] = ffma2(ud, cA, A[28]); A[29] = ffma2(ud, cB, A[29]);
                A[30] = ffma2(ud, cC, A[30]); A[31] = ffma2(ud, cD, A[31]);
            }
            // scale by d1[b]
            {
                const int b0 = 4 * tcg, b2 = 32 + 4 * tcg;
                const ull s0 = pk2(d1b[2 * b0 + tr],       d1b[2 * (b0 + 1) + tr]);
                const ull s1 = pk2(d1b[2 * (b0 + 2) + tr], d1b[2 * (b0 + 3) + tr]);
                const ull s2 = pk2(d1b[2 * b2 + tr],       d1b[2 * (b2 + 1) + tr]);
                const ull s3 = pk2(d1b[2 * (b2 + 2) + tr], d1b[2 * (b2 + 3) + tr]);
                #pragma unroll
                for (int k = 0; k < 8; ++k) {
                    A[k * 4 + 0] = fmul2(A[k * 4 + 0], s0);
                    A[k * 4 + 1] = fmul2(A[k * 4 + 1], s1);
                    A[k * 4 + 2] = fmul2(A[k * 4 + 2], s2);
                    A[k * 4 + 3] = fmul2(A[k * 4 + 3], s3);
                }
            }

            // ===== tangent pass 2: dl += sum_c  (sum_tx n[c][tx]*A[tx][:]) . M2T[c][:] =====
            ull dl2 = 0ull;
            #pragma unroll 2
            for (int c = 0; c < 64; ++c) {
                const float4 n0 = *(const float4*)(sm + O_M3 + c * 16 + 8 * tth);
                const float4 n1 = *(const float4*)(sm + O_M3 + c * 16 + 8 * tth + 4);
                const float d2v = d2b[2 * c + tr];
                const float4 w01 = *(const float4*)(sm + O_M2T + c * 64 + 4 * tcg);
                const float4 w23 = *(const float4*)(sm + O_M2T + c * 64 + 32 + 4 * tcg);
                ull v0 = 0ull, v1 = 0ull, v2 = 0ull, v3 = 0ull;
                ull nd;
                nd = pkdup(n0.x * d2v);
                v0 = ffma2(nd, A[0],  v0); v1 = ffma2(nd, A[1],  v1);
                v2 = ffma2(nd, A[2],  v2); v3 = ffma2(nd, A[3],  v3);
                nd = pkdup(n0.y * d2v);
                v0 = ffma2(nd, A[4],  v0); v1 = ffma2(nd, A[5],  v1);
                v2 = ffma2(nd, A[6],  v2); v3 = ffma2(nd, A[7],  v3);
                nd = pkdup(n0.z * d2v);
                v0 = ffma2(nd, A[8],  v0); v1 = ffma2(nd, A[9],  v1);
                v2 = ffma2(nd, A[10], v2); v3 = ffma2(nd, A[11], v3);
                nd = pkdup(n0.w * d2v);
                v0 = ffma2(nd, A[12], v0); v1 = ffma2(nd, A[13], v1);
                v2 = ffma2(nd, A[14], v2); v3 = ffma2(nd, A[15], v3);
                nd = pkdup(n1.x * d2v);
                v0 = ffma2(nd, A[16], v0); v1 = ffma2(nd, A[17], v1);
                v2 = ffma2(nd, A[18], v2); v3 = ffma2(nd, A[19], v3);
                nd = pkdup(n1.y * d2v);
                v0 = ffma2(nd, A[20], v0); v1 = ffma2(nd, A[21], v1);
                v2 = ffma2(nd, A[22], v2); v3 = ffma2(nd, A[23], v3);
                nd = pkdup(n1.z * d2v);
                v0 = ffma2(nd, A[24], v0); v1 = ffma2(nd, A[25], v1);
                v2 = ffma2(nd, A[26], v2); v3 = ffma2(nd, A[27], v3);
                nd = pkdup(n1.w * d2v);
                v0 = ffma2(nd, A[28], v0); v1 = ffma2(nd, A[29], v1);
                v2 = ffma2(nd, A[30], v2); v3 = ffma2(nd, A[31], v3);

                dl2 = ffma2(v0, pk2(w01.x, w01.y), dl2);
                dl2 = ffma2(v1, pk2(w01.z, w01.w), dl2);
                dl2 = ffma2(v2, pk2(w23.x, w23.y), dl2);
                dl2 = ffma2(v3, pk2(w23.z, w23.w), dl2);
            }

            float dlo, dhi; upk(dl2, dlo, dhi);
            float dl = dlo + dhi;
            float dv = dx * dx;
            #pragma unroll
            for (int m = 1; m <= 8; m <<= 1) {
                dl += __shfl_xor_sync(0xffffffffu, dl, m);
                dv += __shfl_xor_sync(0xffffffffu, dv, m);
            }
            dv *= 0.5f;

            ksx += wq * dx;
            ksl += wq * dl;
            ksv += wq * dv;
            kxp = dx;
        }

        const float scl = hstep * (1.f / 6.f);
        x_state += scl * ksx;
        l_state += scl * ksl;
        v_state += scl * ksv;
        out[(step + 1) * BATCH * Dd + (grow0 + sr) * Dd + se] = x_state;
    }

    if (se == 0) {
        const int base = 3 * BATCH * Dd;
        out[base + grow0 + sr] = l_state;
        out[base + BATCH + grow0 + sr] = fabsf(v_state);
        out[base + 2 * BATCH + grow0 + sr] = 0.f;
    }
}

extern "C" void kernel_launch(void* const* d_in, const int* in_sizes, int n_in,
                              void* d_out, int out_size) {
    const float* ts  = (const float*)d_in[0];
    const float* x0  = (const float*)d_in[1];
    const float* W0  = (const float*)d_in[2];
    const float* b0  = (const float*)d_in[3];
    const float* g0  = (const float*)d_in[4];
    const float* gb0 = (const float*)d_in[5];
    const float* hb0 = (const float*)d_in[6];
    const float* W1  = (const float*)d_in[7];
    const float* b1  = (const float*)d_in[8];
    const float* g1  = (const float*)d_in[9];
    const float* gb1 = (const float*)d_in[10];
    const float* hb1 = (const float*)d_in[11];
    const float* W2  = (const float*)d_in[12];
    const float* b2  = (const float*)d_in[13];
    const float* g2  = (const float*)d_in[14];
    const float* gb2 = (const float*)d_in[15];
    const float* hb2 = (const float*)d_in[16];
    const float* W3  = (const float*)d_in[17];
    const float* b3  = (const float*)d_in[18];
    const float* g3  = (const float*)d_in[19];
    const float* gb3 = (const float*)d_in[20];
    const float* hb3 = (const float*)d_in[21];
    float* out = (float*)d_out;

    build_kernel<<<8, NTHREADS>>>(ts,
        W0, b0, g0, gb0, hb0,
        W1, b1, g1, gb1, hb1,
        W2, b2, g2, gb2, hb2,
        W3, b3, g3, gb3, hb3);

    cudaFuncSetAttribute(traj_kernel, cudaFuncAttributeMaxDynamicSharedMemorySize, SMEM_BYTES);
    traj_kernel<<<BATCH / ROWS, NTHREADS, SMEM_BYTES>>>(ts, x0, out);
}